// round 16
// baseline (speedup 1.0000x reference)
#include <cuda_runtime.h>
#include <cuda_bf16.h>
#include <stdint.h>

// Problem constants
#define BATCH   32
#define NPTS    256
#define LATENT  256
#define BOOK    512
#define NCL     10
#define BN      (BATCH*NPTS)          // 8192
#define CKDIM   (NCL*BOOK)            // 5120
#define TOTALE  (BATCH*NCL*NPTS*BOOK) // 41943040
#define NROWS   (BATCH*NCL*NPTS)      // 81920
#define KSPLIT  8
#define KPART   (CKDIM/KSPLIT)        // 640

// Output layout (flattened tuple: zq, precision_q, prob, log_prob)
// NOTE: PROB_OFF/LP_OFF are ODD -> prob/log_prob stores must be scalar.
#define ZQ_SIZE   (BATCH*NPTS*LATENT)     // 2097152
#define PROB_OFF  (ZQ_SIZE + 1)
#define LP_OFF    (PROB_OFF + BATCH*NPTS*BOOK)

// Scratch (device globals)
__device__ __align__(16) float g_logits_c[TOTALE];   // [b,C,n,K]
__device__ __align__(16) float g_gum[TOTALE];        // gumbels (made in gemm1 ws-warps)
__device__ __align__(16) float g_zq_part[(size_t)KSPLIT*BN*LATENT];
__device__ __align__(16) float g_zn2[BN];
__device__ __align__(16) float g_bn2[CKDIM];
__device__ uint32_t g_rowmax_u[NROWS];               // mapped-uint row max of L
__device__ float g_cprob[BATCH*NCL];
__device__ float g_pq[1];
// bf16 2-way splits
__device__ __align__(16) __nv_bfloat16 g_ze1[BN*LATENT];
__device__ __align__(16) __nv_bfloat16 g_ze2[BN*LATENT];
__device__ __align__(16) __nv_bfloat16 g_b1[CKDIM*LATENT];
__device__ __align__(16) __nv_bfloat16 g_b2[CKDIM*LATENT];
__device__ __align__(16) __nv_bfloat16 g_enc1[(size_t)BN*CKDIM];
__device__ __align__(16) __nv_bfloat16 g_enc2[(size_t)BN*CKDIM];

// monotone float<->uint mapping for atomicMax on floats of any sign
__device__ __forceinline__ uint32_t fmap(float x) {
  uint32_t u = __float_as_uint(x);
  return (u & 0x80000000u) ? ~u : (u | 0x80000000u);
}
__device__ __forceinline__ float funmap(uint32_t u) {
  uint32_t bits = (u & 0x80000000u) ? (u ^ 0x80000000u) : ~u;
  return __uint_as_float(bits);
}

// ---------------- PTX helpers ----------------
__device__ __forceinline__ uint32_t smem_u32(const void* p) {
  uint32_t a;
  asm("{ .reg .u64 t; cvta.to.shared.u64 t, %1; cvt.u32.u64 %0, t; }" : "=r"(a) : "l"(p));
  return a;
}
__device__ __forceinline__ void ldm_x4(uint32_t r[4], uint32_t addr) {
  asm volatile("ldmatrix.sync.aligned.m8n8.x4.shared.b16 {%0,%1,%2,%3}, [%4];"
               : "=r"(r[0]), "=r"(r[1]), "=r"(r[2]), "=r"(r[3]) : "r"(addr));
}
__device__ __forceinline__ void ldm_x4_t(uint32_t r[4], uint32_t addr) {
  asm volatile("ldmatrix.sync.aligned.m8n8.x4.trans.shared.b16 {%0,%1,%2,%3}, [%4];"
               : "=r"(r[0]), "=r"(r[1]), "=r"(r[2]), "=r"(r[3]) : "r"(addr));
}
__device__ __forceinline__ void mma16816(float d[4], const uint32_t a[4],
                                         const uint32_t b0, const uint32_t b1) {
  asm volatile(
    "mma.sync.aligned.m16n8k16.row.col.f32.bf16.bf16.f32 "
    "{%0,%1,%2,%3}, {%4,%5,%6,%7}, {%8,%9}, {%0,%1,%2,%3};"
    : "+f"(d[0]), "+f"(d[1]), "+f"(d[2]), "+f"(d[3])
    : "r"(a[0]), "r"(a[1]), "r"(a[2]), "r"(a[3]), "r"(b0), "r"(b1));
}
__device__ __forceinline__ void cp16(uint32_t smem_addr, const void* gptr) {
  asm volatile("cp.async.cg.shared.global [%0], [%1], 16;"
               :: "r"(smem_addr), "l"(gptr) : "memory");
}
#define CP_COMMIT()  asm volatile("cp.async.commit_group;" ::: "memory")
#define CP_WAIT(n)   asm volatile("cp.async.wait_group %0;" :: "n"(n) : "memory")
// Named barrier for the 8 GEMM warps only (threads 0-255).
#define GEMM_BAR()   asm volatile("bar.sync 1, 256;" ::: "memory")

// ---------------- threefry2x32 (JAX exact) ----------------
__host__ __device__ __forceinline__ void threefry2x32(
    uint32_t k0, uint32_t k1, uint32_t x0, uint32_t x1,
    uint32_t& o0, uint32_t& o1) {
  uint32_t ks2 = 0x1BD11BDAu ^ k0 ^ k1;
  x0 += k0; x1 += k1;
#define TF_ROT(r) { x0 += x1; x1 = (x1 << (r)) | (x1 >> (32-(r))); x1 ^= x0; }
  TF_ROT(13) TF_ROT(15) TF_ROT(26) TF_ROT(6)
  x0 += k1;  x1 += ks2 + 1u;
  TF_ROT(17) TF_ROT(29) TF_ROT(16) TF_ROT(24)
  x0 += ks2; x1 += k0 + 2u;
  TF_ROT(13) TF_ROT(15) TF_ROT(26) TF_ROT(6)
  x0 += k0;  x1 += k1 + 3u;
  TF_ROT(17) TF_ROT(29) TF_ROT(16) TF_ROT(24)
  x0 += k1;  x1 += ks2 + 4u;
  TF_ROT(13) TF_ROT(15) TF_ROT(26) TF_ROT(6)
  x0 += ks2; x1 += k0 + 5u;
#undef TF_ROT
  o0 = x0; o1 = x1;
}
__device__ __forceinline__ float unit_from_bits(uint32_t bits) {
  return __uint_as_float((bits >> 9) | 0x3f800000u) - 1.0f;
}
// Hybrid accurate gumbel (see R11/R12 analysis). Bounds: g in [-3.14, 23.03].
__device__ __forceinline__ float gumbel_from_bits(uint32_t bits) {
  float u = unit_from_bits(bits);
  float d = 1.0f - u;
  float poly = d*(1.0f + d*(0.5f + d*(0.33333334f + d*(0.25f +
               d*(0.2f + d*(0.16666667f + d*0.14285715f))))));
  float mufu = -__logf(u + 1e-10f);
  float inner = (d <= 0.25f) ? poly : mufu;     // inner = -log(u+eps) >= 0
  return -__logf(inner + 1e-10f);
}
__device__ __forceinline__ uint32_t rand_bits(uint32_t k0, uint32_t k1, uint32_t j) {
  uint32_t o0, o1;
  threefry2x32(k0, k1, 0u, j, o0, o1);
  return o0 ^ o1;
}

// ---------------- K0 ----------------
__global__ void k0_cprob(const float* __restrict__ c_logits,
                         const float* __restrict__ lpq,
                         const float* __restrict__ lpqc,
                         float* __restrict__ d_out,
                         uint32_t kc0, uint32_t kc1) {
  __shared__ float gsh[BATCH*NCL];
  int t = threadIdx.x;
  if (t < BATCH*NCL) gsh[t] = gumbel_from_bits(rand_bits(kc0, kc1, (uint32_t)t));
  float pq  = 0.5f / fmaxf(1.0f + expf(lpq[0]),  1e-10f);
  float pqc = 0.5f / fmaxf(1.0f + expf(lpqc[0]), 1e-10f);
  if (t == 0) { g_pq[0] = pq; d_out[ZQ_SIZE] = pq; }
  __syncthreads();
  if (t < BATCH) {
    float y[NCL];
    float m = -3.4e38f;
#pragma unroll
    for (int c = 0; c < NCL; c++) {
      y[c] = (c_logits[t*NCL + c] * pqc + gsh[t*NCL + c]) * 2.0f;
      m = fmaxf(m, y[c]);
    }
    float s = 0.f;
#pragma unroll
    for (int c = 0; c < NCL; c++) { y[c] = expf(y[c] - m); s += y[c]; }
    float inv = 1.0f / s;
#pragma unroll
    for (int c = 0; c < NCL; c++) g_cprob[t*NCL + c] = y[c] * inv;
  }
}

// ---------------- prep: fused norms + bf16 split + rowmax init --------------
__global__ __launch_bounds__(256) void k_prep(const float* __restrict__ ze,
                                              const float* __restrict__ books) {
  int gtid = blockIdx.x * 256 + threadIdx.x;
  if (gtid < NROWS) g_rowmax_u[gtid] = fmap(-3.4e38f);
  int warp = gtid >> 5;
  int lane = gtid & 31;
  if (warp >= BN + CKDIM) return;
  const float* row;
  __nv_bfloat16 *o1, *o2;
  int ridx;
  if (warp < BN) { ridx = warp; row = ze + (size_t)ridx * LATENT; o1 = g_ze1; o2 = g_ze2; }
  else { ridx = warp - BN; row = books + (size_t)ridx * LATENT; o1 = g_b1; o2 = g_b2; }

  float4 v0 = *(const float4*)(row + lane*8);
  float4 v1 = *(const float4*)(row + lane*8 + 4);
  float x[8] = {v0.x, v0.y, v0.z, v0.w, v1.x, v1.y, v1.z, v1.w};
  unsigned short a1[8], a2[8];
  float s = 0.f;
#pragma unroll
  for (int j = 0; j < 8; j++) {
    s += x[j] * x[j];
    __nv_bfloat16 h1 = __float2bfloat16(x[j]);
    float r = x[j] - __bfloat162float(h1);
    __nv_bfloat16 h2 = __float2bfloat16(r);
    a1[j] = *(unsigned short*)&h1;
    a2[j] = *(unsigned short*)&h2;
  }
  uint4 p1, p2;
  p1.x = a1[0] | ((uint32_t)a1[1] << 16); p1.y = a1[2] | ((uint32_t)a1[3] << 16);
  p1.z = a1[4] | ((uint32_t)a1[5] << 16); p1.w = a1[6] | ((uint32_t)a1[7] << 16);
  p2.x = a2[0] | ((uint32_t)a2[1] << 16); p2.y = a2[2] | ((uint32_t)a2[3] << 16);
  p2.z = a2[4] | ((uint32_t)a2[5] << 16); p2.w = a2[6] | ((uint32_t)a2[7] << 16);
  *(uint4*)(o1 + (size_t)ridx * LATENT + lane*8) = p1;
  *(uint4*)(o2 + (size_t)ridx * LATENT + lane*8) = p2;
#pragma unroll
  for (int o = 16; o; o >>= 1) s += __shfl_xor_sync(0xffffffffu, s, o);
  if (lane == 0) { if (warp < BN) g_zn2[warp] = s; else g_bn2[warp - BN] = s; }
}

// ======== GEMM1 (warp-specialized: 8 GEMM warps + 8 gumbel warps) ========
// Threads 0-255: HMMA bf16-split GEMM (named barrier 1). Threads 256-511:
// generate the CTA tile's 8192 gumbels into g_gum, barrier-free, filling
// issue slots the GEMM warps leave idle.
#define G1_ASTR 144
#define G1_A1 0u
#define G1_A2 18432u
#define G1_B1 36864u
#define G1_B2 46080u
#define G1_STAGE 55296u
#define G1_SMEM (2*55296)

__device__ __forceinline__ void g1_load_chunk(uint32_t smb, int st, int mb, int nb,
                                              int k0, int t) {
  uint32_t sb = smb + (uint32_t)st * G1_STAGE;
#pragma unroll
  for (int it = 0; it < 4; it++) {
    int idx = it * 256 + t, row = idx >> 3, q = idx & 7;
    uint32_t roff = (uint32_t)(row * G1_ASTR + q * 16);
    cp16(sb + G1_A1 + roff, g_ze1 + (size_t)(mb + row)*LATENT + k0 + q*8);
    cp16(sb + G1_A2 + roff, g_ze2 + (size_t)(mb + row)*LATENT + k0 + q*8);
  }
#pragma unroll
  for (int it = 0; it < 2; it++) {
    int idx = it * 256 + t, row = idx >> 3, q = idx & 7;
    uint32_t roff = (uint32_t)(row * G1_ASTR + q * 16);
    cp16(sb + G1_B1 + roff, g_b1 + (size_t)(nb + row)*LATENT + k0 + q*8);
    cp16(sb + G1_B2 + roff, g_b2 + (size_t)(nb + row)*LATENT + k0 + q*8);
  }
  CP_COMMIT();
}

__global__ __launch_bounds__(512, 1) void k_gemm1_h(uint32_t ke0, uint32_t ke1) {
  extern __shared__ char sm[];
  uint32_t smb = smem_u32(sm);
  int t = threadIdx.x;
  int mb = blockIdx.x * 128, nb = blockIdx.y * 64;
  int cl = nb >> 9;
  int kbase = nb & 511;

  if (t >= 256) {
    // ---- gumbel role: 256 threads, 32 elements each (tile 128m x 64k) ----
    int u = t - 256;
    int row = u >> 1;                       // 0..127
    int m = mb + row;
    int bi = m >> 8, ni = m & 255;
    uint32_t jb = (uint32_t)((((bi*NCL + cl)*NPTS) + ni)*BOOK + kbase + (u & 1)*32);
#pragma unroll 4
    for (int e = 0; e < 32; e += 2) {
      float ga = gumbel_from_bits(rand_bits(ke0, ke1, jb + (uint32_t)e));
      float gb = gumbel_from_bits(rand_bits(ke0, ke1, jb + (uint32_t)e + 1u));
      *(float2*)&g_gum[jb + e] = make_float2(ga, gb);
    }
    return;
  }

  // ---- GEMM role: threads 0-255, named barrier 1 ----
  int lane = t & 31, wid = t >> 5;
  int wm = wid >> 1, wn = wid & 1;

  float acc[2][4][4];
#pragma unroll
  for (int i = 0; i < 2; i++)
#pragma unroll
    for (int j = 0; j < 4; j++)
#pragma unroll
      for (int q = 0; q < 4; q++) acc[i][j][q] = 0.f;

  g1_load_chunk(smb, 0, mb, nb, 0, t);

  for (int ch = 0; ch < 4; ch++) {
    if (ch < 3) {
      g1_load_chunk(smb, (ch + 1) & 1, mb, nb, (ch + 1) * 64, t);
      CP_WAIT(1);
    } else {
      CP_WAIT(0);
    }
    GEMM_BAR();
    uint32_t sb = smb + (uint32_t)(ch & 1) * G1_STAGE;

#pragma unroll
    for (int s = 0; s < 4; s++) {
      uint32_t a1[2][4], a2[2][4];
      uint32_t arow = (uint32_t)(wm*32 + (lane & 15));
      uint32_t aoff = (uint32_t)(s*32 + (lane >> 4)*16);
#pragma unroll
      for (int fm = 0; fm < 2; fm++) {
        ldm_x4(a1[fm], sb + G1_A1 + (arow + fm*16)*G1_ASTR + aoff);
        ldm_x4(a2[fm], sb + G1_A2 + (arow + fm*16)*G1_ASTR + aoff);
      }
      uint32_t b1[4][2], b2[4][2];
      uint32_t brow = (uint32_t)(wn*32 + ((lane >> 4) * 8) + (lane & 7));
      uint32_t boff = (uint32_t)(s*32 + ((lane >> 3) & 1)*16);
#pragma unroll
      for (int fnb = 0; fnb < 2; fnb++) {
        uint32_t r[4];
        ldm_x4(r, sb + G1_B1 + (brow + fnb*16)*G1_ASTR + boff);
        b1[fnb*2][0] = r[0]; b1[fnb*2][1] = r[1];
        b1[fnb*2+1][0] = r[2]; b1[fnb*2+1][1] = r[3];
        ldm_x4(r, sb + G1_B2 + (brow + fnb*16)*G1_ASTR + boff);
        b2[fnb*2][0] = r[0]; b2[fnb*2][1] = r[1];
        b2[fnb*2+1][0] = r[2]; b2[fnb*2+1][1] = r[3];
      }
#pragma unroll
      for (int fm = 0; fm < 2; fm++)
#pragma unroll
        for (int fn = 0; fn < 4; fn++)
          mma16816(acc[fm][fn], a1[fm], b1[fn][0], b1[fn][1]);
#pragma unroll
      for (int fm = 0; fm < 2; fm++)
#pragma unroll
        for (int fn = 0; fn < 4; fn++)
          mma16816(acc[fm][fn], a1[fm], b2[fn][0], b2[fn][1]);
#pragma unroll
      for (int fm = 0; fm < 2; fm++)
#pragma unroll
        for (int fn = 0; fn < 4; fn++)
          mma16816(acc[fm][fn], a2[fm], b1[fn][0], b1[fn][1]);
    }
    GEMM_BAR();
  }

  float pq = g_pq[0];
#pragma unroll
  for (int fm = 0; fm < 2; fm++) {
    int m0 = mb + wm*32 + fm*16 + (lane >> 2);
    int m1 = m0 + 8;
    float zn0 = g_zn2[m0], zn1 = g_zn2[m1];
    int b0i = m0 >> 8, n0i = m0 & 255;
    int b1i = m1 >> 8, n1i = m1 & 255;
    size_t ob0 = (((size_t)(b0i*NCL + cl))*NPTS + n0i)*BOOK + kbase;
    size_t ob1 = (((size_t)(b1i*NCL + cl))*NPTS + n1i)*BOOK + kbase;
    float mx0 = -3.4e38f, mx1 = -3.4e38f;
#pragma unroll
    for (int fn = 0; fn < 4; fn++) {
      int kk = wn*32 + fn*8 + 2*(lane & 3);
      float2 bn = *(const float2*)&g_bn2[nb + kk];
      float2 o0, o1;
      o0.x = -(zn0 + bn.x - 2.f*acc[fm][fn][0]) * pq;
      o0.y = -(zn0 + bn.y - 2.f*acc[fm][fn][1]) * pq;
      o1.x = -(zn1 + bn.x - 2.f*acc[fm][fn][2]) * pq;
      o1.y = -(zn1 + bn.y - 2.f*acc[fm][fn][3]) * pq;
      mx0 = fmaxf(mx0, fmaxf(o0.x, o0.y));
      mx1 = fmaxf(mx1, fmaxf(o1.x, o1.y));
      *(float2*)&g_logits_c[ob0 + kk] = o0;
      *(float2*)&g_logits_c[ob1 + kk] = o1;
    }
    mx0 = fmaxf(mx0, __shfl_xor_sync(0xffffffffu, mx0, 1));
    mx0 = fmaxf(mx0, __shfl_xor_sync(0xffffffffu, mx0, 2));
    mx1 = fmaxf(mx1, __shfl_xor_sync(0xffffffffu, mx1, 1));
    mx1 = fmaxf(mx1, __shfl_xor_sync(0xffffffffu, mx1, 2));
    if ((lane & 3) == 0) {
      atomicMax(&g_rowmax_u[(b0i*NCL + cl)*NPTS + n0i], fmap(mx0));
      atomicMax(&g_rowmax_u[(b1i*NCL + cl)*NPTS + n1i], fmap(mx1));
    }
  }
}

// ---------------- block reductions ----------------
template<bool IS_MAX>
__device__ __forceinline__ float blockReduce(float v, float* red) {
#pragma unroll
  for (int o = 16; o; o >>= 1) {
    float x = __shfl_xor_sync(0xffffffffu, v, o);
    v = IS_MAX ? fmaxf(v, x) : (v + x);
  }
  int w = threadIdx.x >> 5;
  __syncthreads();
  if ((threadIdx.x & 31) == 0) red[w] = v;
  __syncthreads();
  float r = red[0];
#pragma unroll
  for (int i = 1; i < 8; i++) r = IS_MAX ? fmaxf(r, red[i]) : (r + red[i]);
  return r;
}

// ---------------- K2: encoding (reads precomputed gumbels; R14-proven) ------
__global__ __launch_bounds__(256) void k2_encode(float* __restrict__ d_out) {
  int b = blockIdx.x, n = blockIdx.y;
  int t = threadIdx.x;
  __shared__ float red[8];
  __shared__ float cp[NCL];
  __shared__ float msh[NCL];
  if (t < NCL) {
    cp[t] = g_cprob[b*NCL + t];
    msh[t] = 2.0f * (funmap(g_rowmax_u[(b*NCL + t)*NPTS + n]) + 23.1f);
  }
  __syncthreads();

  float w0 = 0.f, w1 = 0.f;

  for (int c = 0; c < NCL; c++) {
    float cpc = cp[c];
    float m = msh[c];
    int j = ((b*NCL + c)*NPTS + n)*BOOK + 2*t;
    float2 L = *(const float2*)&g_logits_c[j];
    float2 G = *(const float2*)&g_gum[j];
    float e0 = __expf((L.x + G.x) * 2.0f - m);
    float e1 = __expf((L.y + G.y) * 2.0f - m);
    float s = blockReduce<false>(e0 + e1, red);
    float r = cpc / s;
    float v0 = e0 * r, v1 = e1 * r;
    __nv_bfloat16 h10 = __float2bfloat16(v0);
    __nv_bfloat16 h11 = __float2bfloat16(v1);
    __nv_bfloat16 h20 = __float2bfloat16(v0 - __bfloat162float(h10));
    __nv_bfloat16 h21 = __float2bfloat16(v1 - __bfloat162float(h11));
    size_t enc_base = ((size_t)(b*NPTS + n))*CKDIM + c*BOOK + 2*t;
    uint32_t p1 = *(unsigned short*)&h10 | ((uint32_t)*(unsigned short*)&h11 << 16);
    uint32_t p2 = *(unsigned short*)&h20 | ((uint32_t)*(unsigned short*)&h21 << 16);
    *(uint32_t*)&g_enc1[enc_base] = p1;
    *(uint32_t*)&g_enc2[enc_base] = p2;
    w0 += L.x * cpc;
    w1 += L.y * cpc;
  }

  float m = blockReduce<true >(fmaxf(w0, w1), red);
  float e0 = __expf(w0 - m), e1 = __expf(w1 - m);
  float s = blockReduce<false>(e0 + e1, red);
  float inv = 1.0f / s, ls = __logf(s);
  int base = (b*NPTS + n)*BOOK + 2*t;
  d_out[PROB_OFF + base]     = e0 * inv;
  d_out[PROB_OFF + base + 1] = e1 * inv;
  d_out[LP_OFF   + base]     = (w0 - m) - ls;
  d_out[LP_OFF   + base + 1] = (w1 - m) - ls;
}

// ======== GEMM2 (HMMA bf16 split, cp.async dbuf, K-split x8) ========
#define G2_ASTR 144
#define G2_BSTR 272
#define G2_A1 0u
#define G2_A2 9216u
#define G2_B1 18432u
#define G2_B2 35840u
#define G2_STAGE 53248u
#define G2_SMEM (2*53248)

__device__ __forceinline__ void g2_load_chunk(uint32_t smb, int st, int mb, int nb,
                                              int k0, int t) {
  uint32_t sb = smb + (uint32_t)st * G2_STAGE;
#pragma unroll
  for (int it = 0; it < 2; it++) {
    int idx = it * 256 + t, row = idx >> 3, q = idx & 7;
    uint32_t roff = (uint32_t)(row * G2_ASTR + q * 16);
    cp16(sb + G2_A1 + roff, g_enc1 + (size_t)(mb + row)*CKDIM + k0 + q*8);
    cp16(sb + G2_A2 + roff, g_enc2 + (size_t)(mb + row)*CKDIM + k0 + q*8);
  }
#pragma unroll
  for (int it = 0; it < 4; it++) {
    int idx = it * 256 + t, row = idx >> 4, q = idx & 15;
    uint32_t roff = (uint32_t)(row * G2_BSTR + q * 16);
    cp16(sb + G2_B1 + roff, g_b1 + (size_t)(k0 + row)*LATENT + nb + q*8);
    cp16(sb + G2_B2 + roff, g_b2 + (size_t)(k0 + row)*LATENT + nb + q*8);
  }
  CP_COMMIT();
}

__global__ __launch_bounds__(256, 2) void k_gemm2_h() {
  extern __shared__ char sm[];
  uint32_t smb = smem_u32(sm);
  int t = threadIdx.x, lane = t & 31, wid = t >> 5;
  int mb = blockIdx.x * 64, nb = blockIdx.y * 128;
  int kp = blockIdx.z;
  int kbase = kp * KPART;
  int wm = wid >> 2, wn = wid & 3;

  float acc[2][4][4];
#pragma unroll
  for (int i = 0; i < 2; i++)
#pragma unroll
    for (int j = 0; j < 4; j++)
#pragma unroll
      for (int q = 0; q < 4; q++) acc[i][j][q] = 0.f;

  g2_load_chunk(smb, 0, mb, nb, kbase, t);

  for (int ch = 0; ch < KPART/64; ch++) {
    if (ch < KPART/64 - 1) {
      g2_load_chunk(smb, (ch + 1) & 1, mb, nb, kbase + (ch + 1) * 64, t);
      CP_WAIT(1);
    } else {
      CP_WAIT(0);
    }
    __syncthreads();
    uint32_t sb = smb + (uint32_t)(ch & 1) * G2_STAGE;

#pragma unroll
    for (int s = 0; s < 4; s++) {
      uint32_t a1[2][4], a2[2][4];
      uint32_t arow = (uint32_t)(wm*32 + (lane & 15));
      uint32_t aoff = (uint32_t)(s*32 + (lane >> 4)*16);
#pragma unroll
      for (int fm = 0; fm < 2; fm++) {
        ldm_x4(a1[fm], sb + G2_A1 + (arow + fm*16)*G2_ASTR + aoff);
        ldm_x4(a2[fm], sb + G2_A2 + (arow + fm*16)*G2_ASTR + aoff);
      }
      uint32_t b1[4][2], b2[4][2];
      uint32_t brow = (uint32_t)(s*16 + ((lane >> 3) & 1)*8 + (lane & 7));
      uint32_t bcol = (uint32_t)(wn*32 + (lane >> 4)*8);
#pragma unroll
      for (int fnb = 0; fnb < 2; fnb++) {
        uint32_t r[4];
        ldm_x4_t(r, sb + G2_B1 + brow*G2_BSTR + (bcol + fnb*16)*2);
        b1[fnb*2][0] = r[0]; b1[fnb*2][1] = r[1];
        b1[fnb*2+1][0] = r[2]; b1[fnb*2+1][1] = r[3];
        ldm_x4_t(r, sb + G2_B2 + brow*G2_BSTR + (bcol + fnb*16)*2);
        b2[fnb*2][0] = r[0]; b2[fnb*2][1] = r[1];
        b2[fnb*2+1][0] = r[2]; b2[fnb*2+1][1] = r[3];
      }
#pragma unroll
      for (int fm = 0; fm < 2; fm++)
#pragma unroll
        for (int fn = 0; fn < 4; fn++)
          mma16816(acc[fm][fn], a1[fm], b1[fn][0], b1[fn][1]);
#pragma unroll
      for (int fm = 0; fm < 2; fm++)
#pragma unroll
        for (int fn = 0; fn < 4; fn++)
          mma16816(acc[fm][fn], a1[fm], b2[fn][0], b2[fn][1]);
#pragma unroll
      for (int fm = 0; fm < 2; fm++)
#pragma unroll
        for (int fn = 0; fn < 4; fn++)
          mma16816(acc[fm][fn], a2[fm], b1[fn][0], b1[fn][1]);
    }
    __syncthreads();
  }

  size_t pbase = (size_t)kp * BN * LATENT;
#pragma unroll
  for (int fm = 0; fm < 2; fm++) {
    size_t m0 = mb + wm*32 + fm*16 + (lane >> 2);
    size_t m1 = m0 + 8;
#pragma unroll
    for (int fn = 0; fn < 4; fn++) {
      int col = nb + wn*32 + fn*8 + 2*(lane & 3);
      *(float2*)&g_zq_part[pbase + m0*LATENT + col] =
          make_float2(acc[fm][fn][0], acc[fm][fn][1]);
      *(float2*)&g_zq_part[pbase + m1*LATENT + col] =
          make_float2(acc[fm][fn][2], acc[fm][fn][3]);
    }
  }
}

// ---------------- zq reduce: sum the 8 K-split partials ----------------
__global__ __launch_bounds__(256) void k_zqred(float* __restrict__ d_out) {
  size_t i = ((size_t)blockIdx.x * 256 + threadIdx.x) * 4;
  float4 s = *(const float4*)&g_zq_part[i];
#pragma unroll
  for (int p = 1; p < KSPLIT; p++) {
    float4 v = *(const float4*)&g_zq_part[(size_t)p * BN * LATENT + i];
    s.x += v.x; s.y += v.y; s.z += v.z; s.w += v.w;
  }
  *(float4*)&d_out[i] = s;
}

// ---------------- launch ----------------
extern "C" void kernel_launch(void* const* d_in, const int* in_sizes, int n_in,
                              void* d_out_v, int out_size) {
  (void)in_sizes; (void)n_in; (void)out_size;
  const float* ze       = (const float*)d_in[0];
  const float* c_logits = (const float*)d_in[1];
  const float* books    = (const float*)d_in[2];
  const float* lpq      = (const float*)d_in[3];
  const float* lpqc     = (const float*)d_in[4];
  float* d_out = (float*)d_out_v;

  uint32_t kc0, kc1, ke0, ke1;
  threefry2x32(0u, 42u, 0u, 0u, kc0, kc1);
  threefry2x32(0u, 42u, 0u, 1u, ke0, ke1);

  static int attr_done = 0;
  if (!attr_done) {
    cudaFuncSetAttribute(k_gemm1_h, cudaFuncAttributeMaxDynamicSharedMemorySize, G1_SMEM);
    cudaFuncSetAttribute(k_gemm2_h, cudaFuncAttributeMaxDynamicSharedMemorySize, G2_SMEM);
    attr_done = 1;
  }

  k0_cprob<<<1, 320>>>(c_logits, lpq, lpqc, d_out, kc0, kc1);
  {
    int rows = BN + CKDIM;
    int blocks = (rows + 7) / 8;
    k_prep<<<blocks, 256>>>(ze, books);
  }
  k_gemm1_h<<<dim3(BN/128, CKDIM/64), 512, G1_SMEM>>>(ke0, ke1);
  k2_encode<<<dim3(BATCH, NPTS), 256>>>(d_out);
  k_gemm2_h<<<dim3(BN/64, LATENT/128, KSPLIT), 256, G2_SMEM>>>();
  k_zqred<<<(BN*LATENT)/(256*4), 256>>>(d_out);
}

// round 17
// speedup vs baseline: 1.2064x; 1.2064x over previous
#include <cuda_runtime.h>
#include <cuda_bf16.h>
#include <stdint.h>

// Problem constants
#define BATCH   32
#define NPTS    256
#define LATENT  256
#define BOOK    512
#define NCL     10
#define BN      (BATCH*NPTS)          // 8192
#define CKDIM   (NCL*BOOK)            // 5120
#define TOTALE  (BATCH*NCL*NPTS*BOOK) // 41943040
#define NROWS   (BATCH*NCL*NPTS)      // 81920
#define KSPLIT  8
#define KPART   (CKDIM/KSPLIT)        // 640

// Output layout (flattened tuple: zq, precision_q, prob, log_prob)
// NOTE: PROB_OFF/LP_OFF are ODD -> prob/log_prob stores must be scalar.
#define ZQ_SIZE   (BATCH*NPTS*LATENT)     // 2097152
#define PROB_OFF  (ZQ_SIZE + 1)
#define LP_OFF    (PROB_OFF + BATCH*NPTS*BOOK)

// Scratch (device globals)
__device__ __align__(16) float g_logits_c[TOTALE];   // [b,C,n,K]
__device__ __align__(16) float g_zq_part[(size_t)KSPLIT*BN*LATENT];
__device__ __align__(16) float g_zn2[BN];
__device__ __align__(16) float g_bn2[CKDIM];
__device__ uint32_t g_rowmax_u[NROWS];               // mapped-uint row max of L
__device__ float g_cprob[BATCH*NCL];
__device__ float g_pq[1];
// bf16 2-way splits
__device__ __align__(16) __nv_bfloat16 g_ze1[BN*LATENT];
__device__ __align__(16) __nv_bfloat16 g_ze2[BN*LATENT];
__device__ __align__(16) __nv_bfloat16 g_b1[CKDIM*LATENT];
__device__ __align__(16) __nv_bfloat16 g_b2[CKDIM*LATENT];
__device__ __align__(16) __nv_bfloat16 g_enc1[(size_t)BN*CKDIM];
__device__ __align__(16) __nv_bfloat16 g_enc2[(size_t)BN*CKDIM];

// monotone float<->uint mapping for atomicMax on floats of any sign
__device__ __forceinline__ uint32_t fmap(float x) {
  uint32_t u = __float_as_uint(x);
  return (u & 0x80000000u) ? ~u : (u | 0x80000000u);
}
__device__ __forceinline__ float funmap(uint32_t u) {
  uint32_t bits = (u & 0x80000000u) ? (u ^ 0x80000000u) : ~u;
  return __uint_as_float(bits);
}

// ---------------- PTX helpers ----------------
__device__ __forceinline__ uint32_t smem_u32(const void* p) {
  uint32_t a;
  asm("{ .reg .u64 t; cvta.to.shared.u64 t, %1; cvt.u32.u64 %0, t; }" : "=r"(a) : "l"(p));
  return a;
}
__device__ __forceinline__ void ldm_x4(uint32_t r[4], uint32_t addr) {
  asm volatile("ldmatrix.sync.aligned.m8n8.x4.shared.b16 {%0,%1,%2,%3}, [%4];"
               : "=r"(r[0]), "=r"(r[1]), "=r"(r[2]), "=r"(r[3]) : "r"(addr));
}
__device__ __forceinline__ void ldm_x4_t(uint32_t r[4], uint32_t addr) {
  asm volatile("ldmatrix.sync.aligned.m8n8.x4.trans.shared.b16 {%0,%1,%2,%3}, [%4];"
               : "=r"(r[0]), "=r"(r[1]), "=r"(r[2]), "=r"(r[3]) : "r"(addr));
}
__device__ __forceinline__ void mma16816(float d[4], const uint32_t a[4],
                                         const uint32_t b0, const uint32_t b1) {
  asm volatile(
    "mma.sync.aligned.m16n8k16.row.col.f32.bf16.bf16.f32 "
    "{%0,%1,%2,%3}, {%4,%5,%6,%7}, {%8,%9}, {%0,%1,%2,%3};"
    : "+f"(d[0]), "+f"(d[1]), "+f"(d[2]), "+f"(d[3])
    : "r"(a[0]), "r"(a[1]), "r"(a[2]), "r"(a[3]), "r"(b0), "r"(b1));
}
__device__ __forceinline__ void cp16(uint32_t smem_addr, const void* gptr) {
  asm volatile("cp.async.cg.shared.global [%0], [%1], 16;"
               :: "r"(smem_addr), "l"(gptr) : "memory");
}
#define CP_COMMIT()  asm volatile("cp.async.commit_group;" ::: "memory")
#define CP_WAIT(n)   asm volatile("cp.async.wait_group %0;" :: "n"(n) : "memory")

// ---------------- threefry2x32 (JAX exact) ----------------
__host__ __device__ __forceinline__ void threefry2x32(
    uint32_t k0, uint32_t k1, uint32_t x0, uint32_t x1,
    uint32_t& o0, uint32_t& o1) {
  uint32_t ks2 = 0x1BD11BDAu ^ k0 ^ k1;
  x0 += k0; x1 += k1;
#define TF_ROT(r) { x0 += x1; x1 = (x1 << (r)) | (x1 >> (32-(r))); x1 ^= x0; }
  TF_ROT(13) TF_ROT(15) TF_ROT(26) TF_ROT(6)
  x0 += k1;  x1 += ks2 + 1u;
  TF_ROT(17) TF_ROT(29) TF_ROT(16) TF_ROT(24)
  x0 += ks2; x1 += k0 + 2u;
  TF_ROT(13) TF_ROT(15) TF_ROT(26) TF_ROT(6)
  x0 += k0;  x1 += k1 + 3u;
  TF_ROT(17) TF_ROT(29) TF_ROT(16) TF_ROT(24)
  x0 += k1;  x1 += ks2 + 4u;
  TF_ROT(13) TF_ROT(15) TF_ROT(26) TF_ROT(6)
  x0 += ks2; x1 += k0 + 5u;
#undef TF_ROT
  o0 = x0; o1 = x1;
}
__device__ __forceinline__ float unit_from_bits(uint32_t bits) {
  return __uint_as_float((bits >> 9) | 0x3f800000u) - 1.0f;
}
// Hybrid accurate gumbel (see R11/R12 analysis). Bounds: g in [-3.14, 23.03].
__device__ __forceinline__ float gumbel_from_bits(uint32_t bits) {
  float u = unit_from_bits(bits);
  float d = 1.0f - u;
  float poly = d*(1.0f + d*(0.5f + d*(0.33333334f + d*(0.25f +
               d*(0.2f + d*(0.16666667f + d*0.14285715f))))));
  float mufu = -__logf(u + 1e-10f);
  float inner = (d <= 0.25f) ? poly : mufu;     // inner = -log(u+eps) >= 0
  return -__logf(inner + 1e-10f);
}
__device__ __forceinline__ uint32_t rand_bits(uint32_t k0, uint32_t k1, uint32_t j) {
  uint32_t o0, o1;
  threefry2x32(k0, k1, 0u, j, o0, o1);
  return o0 ^ o1;
}

// ---------------- K0 ----------------
__global__ void k0_cprob(const float* __restrict__ c_logits,
                         const float* __restrict__ lpq,
                         const float* __restrict__ lpqc,
                         float* __restrict__ d_out,
                         uint32_t kc0, uint32_t kc1) {
  __shared__ float gsh[BATCH*NCL];
  int t = threadIdx.x;
  if (t < BATCH*NCL) gsh[t] = gumbel_from_bits(rand_bits(kc0, kc1, (uint32_t)t));
  float pq  = 0.5f / fmaxf(1.0f + expf(lpq[0]),  1e-10f);
  float pqc = 0.5f / fmaxf(1.0f + expf(lpqc[0]), 1e-10f);
  if (t == 0) { g_pq[0] = pq; d_out[ZQ_SIZE] = pq; }
  __syncthreads();
  if (t < BATCH) {
    float y[NCL];
    float m = -3.4e38f;
#pragma unroll
    for (int c = 0; c < NCL; c++) {
      y[c] = (c_logits[t*NCL + c] * pqc + gsh[t*NCL + c]) * 2.0f;
      m = fmaxf(m, y[c]);
    }
    float s = 0.f;
#pragma unroll
    for (int c = 0; c < NCL; c++) { y[c] = expf(y[c] - m); s += y[c]; }
    float inv = 1.0f / s;
#pragma unroll
    for (int c = 0; c < NCL; c++) g_cprob[t*NCL + c] = y[c] * inv;
  }
}

// ---------------- prep: fused norms + bf16 split + rowmax init --------------
__global__ __launch_bounds__(256) void k_prep(const float* __restrict__ ze,
                                              const float* __restrict__ books) {
  int gtid = blockIdx.x * 256 + threadIdx.x;
  if (gtid < NROWS) g_rowmax_u[gtid] = fmap(-3.4e38f);
  int warp = gtid >> 5;
  int lane = gtid & 31;
  if (warp >= BN + CKDIM) return;
  const float* row;
  __nv_bfloat16 *o1, *o2;
  int ridx;
  if (warp < BN) { ridx = warp; row = ze + (size_t)ridx * LATENT; o1 = g_ze1; o2 = g_ze2; }
  else { ridx = warp - BN; row = books + (size_t)ridx * LATENT; o1 = g_b1; o2 = g_b2; }

  float4 v0 = *(const float4*)(row + lane*8);
  float4 v1 = *(const float4*)(row + lane*8 + 4);
  float x[8] = {v0.x, v0.y, v0.z, v0.w, v1.x, v1.y, v1.z, v1.w};
  unsigned short a1[8], a2[8];
  float s = 0.f;
#pragma unroll
  for (int j = 0; j < 8; j++) {
    s += x[j] * x[j];
    __nv_bfloat16 h1 = __float2bfloat16(x[j]);
    float r = x[j] - __bfloat162float(h1);
    __nv_bfloat16 h2 = __float2bfloat16(r);
    a1[j] = *(unsigned short*)&h1;
    a2[j] = *(unsigned short*)&h2;
  }
  uint4 p1, p2;
  p1.x = a1[0] | ((uint32_t)a1[1] << 16); p1.y = a1[2] | ((uint32_t)a1[3] << 16);
  p1.z = a1[4] | ((uint32_t)a1[5] << 16); p1.w = a1[6] | ((uint32_t)a1[7] << 16);
  p2.x = a2[0] | ((uint32_t)a2[1] << 16); p2.y = a2[2] | ((uint32_t)a2[3] << 16);
  p2.z = a2[4] | ((uint32_t)a2[5] << 16); p2.w = a2[6] | ((uint32_t)a2[7] << 16);
  *(uint4*)(o1 + (size_t)ridx * LATENT + lane*8) = p1;
  *(uint4*)(o2 + (size_t)ridx * LATENT + lane*8) = p2;
#pragma unroll
  for (int o = 16; o; o >>= 1) s += __shfl_xor_sync(0xffffffffu, s, o);
  if (lane == 0) { if (warp < BN) g_zn2[warp] = s; else g_bn2[warp - BN] = s; }
}

// ======== GEMM1 (HMMA bf16 split, cp.async dbuf, 2 CTA/SM) ========
#define G1_ASTR 144
#define G1_A1 0u
#define G1_A2 18432u
#define G1_B1 36864u
#define G1_B2 46080u
#define G1_STAGE 55296u
#define G1_SMEM (2*55296)

__device__ __forceinline__ void g1_load_chunk(uint32_t smb, int st, int mb, int nb,
                                              int k0, int t) {
  uint32_t sb = smb + (uint32_t)st * G1_STAGE;
#pragma unroll
  for (int it = 0; it < 4; it++) {
    int idx = it * 256 + t, row = idx >> 3, q = idx & 7;
    uint32_t roff = (uint32_t)(row * G1_ASTR + q * 16);
    cp16(sb + G1_A1 + roff, g_ze1 + (size_t)(mb + row)*LATENT + k0 + q*8);
    cp16(sb + G1_A2 + roff, g_ze2 + (size_t)(mb + row)*LATENT + k0 + q*8);
  }
#pragma unroll
  for (int it = 0; it < 2; it++) {
    int idx = it * 256 + t, row = idx >> 3, q = idx & 7;
    uint32_t roff = (uint32_t)(row * G1_ASTR + q * 16);
    cp16(sb + G1_B1 + roff, g_b1 + (size_t)(nb + row)*LATENT + k0 + q*8);
    cp16(sb + G1_B2 + roff, g_b2 + (size_t)(nb + row)*LATENT + k0 + q*8);
  }
  CP_COMMIT();
}

__global__ __launch_bounds__(256, 2) void k_gemm1_h() {
  extern __shared__ char sm[];
  uint32_t smb = smem_u32(sm);
  int t = threadIdx.x, lane = t & 31, wid = t >> 5;
  int mb = blockIdx.x * 128, nb = blockIdx.y * 64;
  int wm = wid >> 1, wn = wid & 1;

  float acc[2][4][4];
#pragma unroll
  for (int i = 0; i < 2; i++)
#pragma unroll
    for (int j = 0; j < 4; j++)
#pragma unroll
      for (int q = 0; q < 4; q++) acc[i][j][q] = 0.f;

  g1_load_chunk(smb, 0, mb, nb, 0, t);

  for (int ch = 0; ch < 4; ch++) {
    if (ch < 3) {
      g1_load_chunk(smb, (ch + 1) & 1, mb, nb, (ch + 1) * 64, t);
      CP_WAIT(1);
    } else {
      CP_WAIT(0);
    }
    __syncthreads();
    uint32_t sb = smb + (uint32_t)(ch & 1) * G1_STAGE;

#pragma unroll
    for (int s = 0; s < 4; s++) {
      uint32_t a1[2][4], a2[2][4];
      uint32_t arow = (uint32_t)(wm*32 + (lane & 15));
      uint32_t aoff = (uint32_t)(s*32 + (lane >> 4)*16);
#pragma unroll
      for (int fm = 0; fm < 2; fm++) {
        ldm_x4(a1[fm], sb + G1_A1 + (arow + fm*16)*G1_ASTR + aoff);
        ldm_x4(a2[fm], sb + G1_A2 + (arow + fm*16)*G1_ASTR + aoff);
      }
      uint32_t b1[4][2], b2[4][2];
      uint32_t brow = (uint32_t)(wn*32 + ((lane >> 4) * 8) + (lane & 7));
      uint32_t boff = (uint32_t)(s*32 + ((lane >> 3) & 1)*16);
#pragma unroll
      for (int fnb = 0; fnb < 2; fnb++) {
        uint32_t r[4];
        ldm_x4(r, sb + G1_B1 + (brow + fnb*16)*G1_ASTR + boff);
        b1[fnb*2][0] = r[0]; b1[fnb*2][1] = r[1];
        b1[fnb*2+1][0] = r[2]; b1[fnb*2+1][1] = r[3];
        ldm_x4(r, sb + G1_B2 + (brow + fnb*16)*G1_ASTR + boff);
        b2[fnb*2][0] = r[0]; b2[fnb*2][1] = r[1];
        b2[fnb*2+1][0] = r[2]; b2[fnb*2+1][1] = r[3];
      }
#pragma unroll
      for (int fm = 0; fm < 2; fm++)
#pragma unroll
        for (int fn = 0; fn < 4; fn++)
          mma16816(acc[fm][fn], a1[fm], b1[fn][0], b1[fn][1]);
#pragma unroll
      for (int fm = 0; fm < 2; fm++)
#pragma unroll
        for (int fn = 0; fn < 4; fn++)
          mma16816(acc[fm][fn], a1[fm], b2[fn][0], b2[fn][1]);
#pragma unroll
      for (int fm = 0; fm < 2; fm++)
#pragma unroll
        for (int fn = 0; fn < 4; fn++)
          mma16816(acc[fm][fn], a2[fm], b1[fn][0], b1[fn][1]);
    }
    __syncthreads();
  }

  float pq = g_pq[0];
  int cl = nb >> 9;
  int kbase = nb & 511;
#pragma unroll
  for (int fm = 0; fm < 2; fm++) {
    int m0 = mb + wm*32 + fm*16 + (lane >> 2);
    int m1 = m0 + 8;
    float zn0 = g_zn2[m0], zn1 = g_zn2[m1];
    int b0i = m0 >> 8, n0i = m0 & 255;
    int b1i = m1 >> 8, n1i = m1 & 255;
    size_t ob0 = (((size_t)(b0i*NCL + cl))*NPTS + n0i)*BOOK + kbase;
    size_t ob1 = (((size_t)(b1i*NCL + cl))*NPTS + n1i)*BOOK + kbase;
    float mx0 = -3.4e38f, mx1 = -3.4e38f;
#pragma unroll
    for (int fn = 0; fn < 4; fn++) {
      int kk = wn*32 + fn*8 + 2*(lane & 3);
      float2 bn = *(const float2*)&g_bn2[nb + kk];
      float2 o0, o1;
      o0.x = -(zn0 + bn.x - 2.f*acc[fm][fn][0]) * pq;
      o0.y = -(zn0 + bn.y - 2.f*acc[fm][fn][1]) * pq;
      o1.x = -(zn1 + bn.x - 2.f*acc[fm][fn][2]) * pq;
      o1.y = -(zn1 + bn.y - 2.f*acc[fm][fn][3]) * pq;
      mx0 = fmaxf(mx0, fmaxf(o0.x, o0.y));
      mx1 = fmaxf(mx1, fmaxf(o1.x, o1.y));
      *(float2*)&g_logits_c[ob0 + kk] = o0;
      *(float2*)&g_logits_c[ob1 + kk] = o1;
    }
    mx0 = fmaxf(mx0, __shfl_xor_sync(0xffffffffu, mx0, 1));
    mx0 = fmaxf(mx0, __shfl_xor_sync(0xffffffffu, mx0, 2));
    mx1 = fmaxf(mx1, __shfl_xor_sync(0xffffffffu, mx1, 1));
    mx1 = fmaxf(mx1, __shfl_xor_sync(0xffffffffu, mx1, 2));
    if ((lane & 3) == 0) {
      atomicMax(&g_rowmax_u[(b0i*NCL + cl)*NPTS + n0i], fmap(mx0));
      atomicMax(&g_rowmax_u[(b1i*NCL + cl)*NPTS + n1i], fmap(mx1));
    }
  }
}

// ---------------- K2: warp-per-row encoding (no block barriers) -------------
// One warp per (b,n) row; lane owns 16 k's (4 float4 groups, k = lane*4+i*128).
// All reductions are warp shuffles; cp/msh broadcast via shfl.
__global__ __launch_bounds__(256) void k2_encode(float* __restrict__ d_out,
                                                 uint32_t ke0, uint32_t ke1) {
  int wid = threadIdx.x >> 5, lane = threadIdx.x & 31;
  int row = blockIdx.x * 8 + wid;          // 0..8191
  int b = row >> 8, n = row & 255;

  float cp_l = 0.f, msh_l = 0.f;
  if (lane < NCL) {
    cp_l = g_cprob[b*NCL + lane];
    msh_l = 2.0f * (funmap(g_rowmax_u[(b*NCL + lane)*NPTS + n]) + 23.1f);
  }

  float w[16];
#pragma unroll
  for (int i = 0; i < 16; i++) w[i] = 0.f;

  for (int c = 0; c < NCL; c++) {
    float cpc = __shfl_sync(0xffffffffu, cp_l, c);
    float mc  = __shfl_sync(0xffffffffu, msh_l, c);
    int j0 = ((b*NCL + c)*NPTS + n)*BOOK;
    float e[16];
    float psum = 0.f;
#pragma unroll
    for (int i = 0; i < 4; i++) {
      int k = lane*4 + i*128;
      float4 L = *(const float4*)&g_logits_c[j0 + k];
      float g0 = gumbel_from_bits(rand_bits(ke0, ke1, (uint32_t)(j0 + k)));
      float g1 = gumbel_from_bits(rand_bits(ke0, ke1, (uint32_t)(j0 + k + 1)));
      float g2 = gumbel_from_bits(rand_bits(ke0, ke1, (uint32_t)(j0 + k + 2)));
      float g3 = gumbel_from_bits(rand_bits(ke0, ke1, (uint32_t)(j0 + k + 3)));
      e[i*4+0] = __expf((L.x + g0) * 2.0f - mc);
      e[i*4+1] = __expf((L.y + g1) * 2.0f - mc);
      e[i*4+2] = __expf((L.z + g2) * 2.0f - mc);
      e[i*4+3] = __expf((L.w + g3) * 2.0f - mc);
      psum += (e[i*4+0] + e[i*4+1]) + (e[i*4+2] + e[i*4+3]);
      w[i*4+0] = fmaf(L.x, cpc, w[i*4+0]);
      w[i*4+1] = fmaf(L.y, cpc, w[i*4+1]);
      w[i*4+2] = fmaf(L.z, cpc, w[i*4+2]);
      w[i*4+3] = fmaf(L.w, cpc, w[i*4+3]);
    }
#pragma unroll
    for (int o = 16; o; o >>= 1) psum += __shfl_xor_sync(0xffffffffu, psum, o);
    float r = cpc / psum;
    size_t eb = ((size_t)(b*NPTS + n))*CKDIM + c*BOOK;
#pragma unroll
    for (int i = 0; i < 4; i++) {
      int k = lane*4 + i*128;
      float v0 = e[i*4+0]*r, v1 = e[i*4+1]*r, v2 = e[i*4+2]*r, v3 = e[i*4+3]*r;
      __nv_bfloat16 h0 = __float2bfloat16(v0), h1 = __float2bfloat16(v1);
      __nv_bfloat16 h2 = __float2bfloat16(v2), h3 = __float2bfloat16(v3);
      __nv_bfloat16 r0 = __float2bfloat16(v0 - __bfloat162float(h0));
      __nv_bfloat16 r1 = __float2bfloat16(v1 - __bfloat162float(h1));
      __nv_bfloat16 r2 = __float2bfloat16(v2 - __bfloat162float(h2));
      __nv_bfloat16 r3 = __float2bfloat16(v3 - __bfloat162float(h3));
      uint2 p1, p2;
      p1.x = *(unsigned short*)&h0 | ((uint32_t)*(unsigned short*)&h1 << 16);
      p1.y = *(unsigned short*)&h2 | ((uint32_t)*(unsigned short*)&h3 << 16);
      p2.x = *(unsigned short*)&r0 | ((uint32_t)*(unsigned short*)&r1 << 16);
      p2.y = *(unsigned short*)&r2 | ((uint32_t)*(unsigned short*)&r3 << 16);
      *(uint2*)&g_enc1[eb + k] = p1;
      *(uint2*)&g_enc2[eb + k] = p2;
    }
  }

  // final row softmax over w[512]
  float mx = w[0];
#pragma unroll
  for (int i = 1; i < 16; i++) mx = fmaxf(mx, w[i]);
#pragma unroll
  for (int o = 16; o; o >>= 1) mx = fmaxf(mx, __shfl_xor_sync(0xffffffffu, mx, o));
  float es[16];
  float ssum = 0.f;
#pragma unroll
  for (int i = 0; i < 16; i++) { es[i] = __expf(w[i] - mx); ssum += es[i]; }
#pragma unroll
  for (int o = 16; o; o >>= 1) ssum += __shfl_xor_sync(0xffffffffu, ssum, o);
  float inv = 1.0f / ssum, ls = __logf(ssum);
  int base = (b*NPTS + n)*BOOK;
#pragma unroll
  for (int i = 0; i < 4; i++) {
    int k = lane*4 + i*128;
#pragma unroll
    for (int q = 0; q < 4; q++) {
      d_out[PROB_OFF + base + k + q] = es[i*4+q] * inv;    // odd base: scalar
      d_out[LP_OFF   + base + k + q] = (w[i*4+q] - mx) - ls;
    }
  }
}

// ======== GEMM2 (HMMA bf16 split, cp.async dbuf, K-split x8) ========
#define G2_ASTR 144
#define G2_BSTR 272
#define G2_A1 0u
#define G2_A2 9216u
#define G2_B1 18432u
#define G2_B2 35840u
#define G2_STAGE 53248u
#define G2_SMEM (2*53248)

__device__ __forceinline__ void g2_load_chunk(uint32_t smb, int st, int mb, int nb,
                                              int k0, int t) {
  uint32_t sb = smb + (uint32_t)st * G2_STAGE;
#pragma unroll
  for (int it = 0; it < 2; it++) {
    int idx = it * 256 + t, row = idx >> 3, q = idx & 7;
    uint32_t roff = (uint32_t)(row * G2_ASTR + q * 16);
    cp16(sb + G2_A1 + roff, g_enc1 + (size_t)(mb + row)*CKDIM + k0 + q*8);
    cp16(sb + G2_A2 + roff, g_enc2 + (size_t)(mb + row)*CKDIM + k0 + q*8);
  }
#pragma unroll
  for (int it = 0; it < 4; it++) {
    int idx = it * 256 + t, row = idx >> 4, q = idx & 15;
    uint32_t roff = (uint32_t)(row * G2_BSTR + q * 16);
    cp16(sb + G2_B1 + roff, g_b1 + (size_t)(k0 + row)*LATENT + nb + q*8);
    cp16(sb + G2_B2 + roff, g_b2 + (size_t)(k0 + row)*LATENT + nb + q*8);
  }
  CP_COMMIT();
}

__global__ __launch_bounds__(256, 2) void k_gemm2_h() {
  extern __shared__ char sm[];
  uint32_t smb = smem_u32(sm);
  int t = threadIdx.x, lane = t & 31, wid = t >> 5;
  int mb = blockIdx.x * 64, nb = blockIdx.y * 128;
  int kp = blockIdx.z;
  int kbase = kp * KPART;
  int wm = wid >> 2, wn = wid & 3;

  float acc[2][4][4];
#pragma unroll
  for (int i = 0; i < 2; i++)
#pragma unroll
    for (int j = 0; j < 4; j++)
#pragma unroll
      for (int q = 0; q < 4; q++) acc[i][j][q] = 0.f;

  g2_load_chunk(smb, 0, mb, nb, kbase, t);

  for (int ch = 0; ch < KPART/64; ch++) {
    if (ch < KPART/64 - 1) {
      g2_load_chunk(smb, (ch + 1) & 1, mb, nb, kbase + (ch + 1) * 64, t);
      CP_WAIT(1);
    } else {
      CP_WAIT(0);
    }
    __syncthreads();
    uint32_t sb = smb + (uint32_t)(ch & 1) * G2_STAGE;

#pragma unroll
    for (int s = 0; s < 4; s++) {
      uint32_t a1[2][4], a2[2][4];
      uint32_t arow = (uint32_t)(wm*32 + (lane & 15));
      uint32_t aoff = (uint32_t)(s*32 + (lane >> 4)*16);
#pragma unroll
      for (int fm = 0; fm < 2; fm++) {
        ldm_x4(a1[fm], sb + G2_A1 + (arow + fm*16)*G2_ASTR + aoff);
        ldm_x4(a2[fm], sb + G2_A2 + (arow + fm*16)*G2_ASTR + aoff);
      }
      uint32_t b1[4][2], b2[4][2];
      uint32_t brow = (uint32_t)(s*16 + ((lane >> 3) & 1)*8 + (lane & 7));
      uint32_t bcol = (uint32_t)(wn*32 + (lane >> 4)*8);
#pragma unroll
      for (int fnb = 0; fnb < 2; fnb++) {
        uint32_t r[4];
        ldm_x4_t(r, sb + G2_B1 + brow*G2_BSTR + (bcol + fnb*16)*2);
        b1[fnb*2][0] = r[0]; b1[fnb*2][1] = r[1];
        b1[fnb*2+1][0] = r[2]; b1[fnb*2+1][1] = r[3];
        ldm_x4_t(r, sb + G2_B2 + brow*G2_BSTR + (bcol + fnb*16)*2);
        b2[fnb*2][0] = r[0]; b2[fnb*2][1] = r[1];
        b2[fnb*2+1][0] = r[2]; b2[fnb*2+1][1] = r[3];
      }
#pragma unroll
      for (int fm = 0; fm < 2; fm++)
#pragma unroll
        for (int fn = 0; fn < 4; fn++)
          mma16816(acc[fm][fn], a1[fm], b1[fn][0], b1[fn][1]);
#pragma unroll
      for (int fm = 0; fm < 2; fm++)
#pragma unroll
        for (int fn = 0; fn < 4; fn++)
          mma16816(acc[fm][fn], a1[fm], b2[fn][0], b2[fn][1]);
#pragma unroll
      for (int fm = 0; fm < 2; fm++)
#pragma unroll
        for (int fn = 0; fn < 4; fn++)
          mma16816(acc[fm][fn], a2[fm], b1[fn][0], b1[fn][1]);
    }
    __syncthreads();
  }

  size_t pbase = (size_t)kp * BN * LATENT;
#pragma unroll
  for (int fm = 0; fm < 2; fm++) {
    size_t m0 = mb + wm*32 + fm*16 + (lane >> 2);
    size_t m1 = m0 + 8;
#pragma unroll
    for (int fn = 0; fn < 4; fn++) {
      int col = nb + wn*32 + fn*8 + 2*(lane & 3);
      *(float2*)&g_zq_part[pbase + m0*LATENT + col] =
          make_float2(acc[fm][fn][0], acc[fm][fn][1]);
      *(float2*)&g_zq_part[pbase + m1*LATENT + col] =
          make_float2(acc[fm][fn][2], acc[fm][fn][3]);
    }
  }
}

// ---------------- zq reduce: sum the 8 K-split partials ----------------
__global__ __launch_bounds__(256) void k_zqred(float* __restrict__ d_out) {
  size_t i = ((size_t)blockIdx.x * 256 + threadIdx.x) * 4;
  float4 s = *(const float4*)&g_zq_part[i];
#pragma unroll
  for (int p = 1; p < KSPLIT; p++) {
    float4 v = *(const float4*)&g_zq_part[(size_t)p * BN * LATENT + i];
    s.x += v.x; s.y += v.y; s.z += v.z; s.w += v.w;
  }
  *(float4*)&d_out[i] = s;
}

// ---------------- launch ----------------
extern "C" void kernel_launch(void* const* d_in, const int* in_sizes, int n_in,
                              void* d_out_v, int out_size) {
  (void)in_sizes; (void)n_in; (void)out_size;
  const float* ze       = (const float*)d_in[0];
  const float* c_logits = (const float*)d_in[1];
  const float* books    = (const float*)d_in[2];
  const float* lpq      = (const float*)d_in[3];
  const float* lpqc     = (const float*)d_in[4];
  float* d_out = (float*)d_out_v;

  uint32_t kc0, kc1, ke0, ke1;
  threefry2x32(0u, 42u, 0u, 0u, kc0, kc1);
  threefry2x32(0u, 42u, 0u, 1u, ke0, ke1);

  static int attr_done = 0;
  if (!attr_done) {
    cudaFuncSetAttribute(k_gemm1_h, cudaFuncAttributeMaxDynamicSharedMemorySize, G1_SMEM);
    cudaFuncSetAttribute(k_gemm2_h, cudaFuncAttributeMaxDynamicSharedMemorySize, G2_SMEM);
    attr_done = 1;
  }

  k0_cprob<<<1, 320>>>(c_logits, lpq, lpqc, d_out, kc0, kc1);
  {
    int rows = BN + CKDIM;
    int blocks = (rows + 7) / 8;
    k_prep<<<blocks, 256>>>(ze, books);
  }
  k_gemm1_h<<<dim3(BN/128, CKDIM/64), 256, G1_SMEM>>>();
  k2_encode<<<BN/8, 256>>>(d_out, ke0, ke1);
  k_gemm2_h<<<dim3(BN/64, LATENT/128, KSPLIT), 256, G2_SMEM>>>();
  k_zqred<<<(BN*LATENT)/(256*4), 256>>>(d_out);
}